// round 1
// baseline (speedup 1.0000x reference)
#include <cuda_runtime.h>
#include <math.h>

#define NMAX 50000
#define EMAX 800000
#define EPMAX (EMAX + NMAX)
#define FH 256
#define NHEADS 4
#define OUTD 64

// ---------------- scratch (device globals; no runtime alloc allowed) ----------
__device__ float g_h[NMAX * FH];      // activation ping
__device__ float g_h2[NMAX * FH];     // activation pong (pre-aggregation h)
__device__ float g_as[NMAX * NHEADS]; // alpha_src per node
__device__ float g_ad[NMAX * NHEADS]; // alpha_dst per node
__device__ int   g_off[NMAX + 1];     // CSR row offsets (by dst)
__device__ int   g_deg[NMAX];
__device__ int   g_cur[NMAX];
__device__ int   g_srcs[EPMAX];       // CSR column indices (src node per edge)

__device__ __forceinline__ float lrelu(float x) { return x > 0.f ? x : 0.2f * x; }

// ---------------- CSR build ---------------------------------------------------
__global__ void k_zero(int n) {
    int i = blockIdx.x * blockDim.x + threadIdx.x;
    if (i < n) { g_deg[i] = 0; g_cur[i] = 0; }
}

__global__ void k_deg(const int* __restrict__ ei, int E, int n) {
    int i = blockIdx.x * blockDim.x + threadIdx.x;
    int tot = E + n;
    if (i < tot) {
        int dst = (i < E) ? ei[E + i] : (i - E);   // self-loops appended
        atomicAdd(&g_deg[dst], 1);
    }
}

__global__ void k_scan(int n) {   // single block, 1024 threads; exclusive scan -> g_off
    __shared__ int s[1024];
    __shared__ int carry;
    int tid = threadIdx.x;
    if (tid == 0) { carry = 0; g_off[0] = 0; }
    __syncthreads();
    for (int base = 0; base < n; base += 1024) {
        int v = (base + tid < n) ? g_deg[base + tid] : 0;
        s[tid] = v;
        __syncthreads();
        for (int off = 1; off < 1024; off <<= 1) {
            int t = (tid >= off) ? s[tid - off] : 0;
            __syncthreads();
            s[tid] += t;
            __syncthreads();
        }
        if (base + tid < n) g_off[base + tid + 1] = carry + s[tid];
        __syncthreads();
        if (tid == 0) carry += s[1023];
        __syncthreads();
    }
}

__global__ void k_scatter(const int* __restrict__ ei, int E, int n) {
    int i = blockIdx.x * blockDim.x + threadIdx.x;
    int tot = E + n;
    if (i < tot) {
        int src, dst;
        if (i < E) { src = ei[i]; dst = ei[E + i]; }
        else       { src = i - E; dst = src; }
        int pos = g_off[dst] + atomicAdd(&g_cur[dst], 1);
        g_srcs[pos] = src;
    }
}

// ---------------- GEMM: C[M,N] = A[M,K] * B[K,N]  (fp32, 64x64 tiles) ---------
__global__ __launch_bounds__(256) void k_gemm(
    const float* __restrict__ A, const float* __restrict__ B, float* __restrict__ C,
    int M, int N, int K)
{
    __shared__ float As[64][17];   // [m][k], padded
    __shared__ float Bs[16][64];   // [k][n]
    int tid = threadIdx.x;
    int tx = tid & 15, ty = tid >> 4;
    int row0 = blockIdx.y * 64;
    int col0 = blockIdx.x * 64;

    float acc[4][4] = {};

    for (int k0 = 0; k0 < K; k0 += 16) {
#pragma unroll
        for (int r = 0; r < 4; r++) {
            int idx = tid + r * 256;
            int m = idx >> 4, kk = idx & 15;
            As[m][kk] = (row0 + m < M) ? A[(row0 + m) * K + k0 + kk] : 0.f;
        }
#pragma unroll
        for (int r = 0; r < 4; r++) {
            int idx = tid + r * 256;
            int kk = idx >> 6, nn = idx & 63;
            Bs[kk][nn] = B[(k0 + kk) * N + col0 + nn];
        }
        __syncthreads();
#pragma unroll
        for (int kk = 0; kk < 16; kk++) {
            float a0 = As[ty * 4 + 0][kk];
            float a1 = As[ty * 4 + 1][kk];
            float a2 = As[ty * 4 + 2][kk];
            float a3 = As[ty * 4 + 3][kk];
            float4 b = *(const float4*)&Bs[kk][tx * 4];
            acc[0][0] = fmaf(a0, b.x, acc[0][0]); acc[0][1] = fmaf(a0, b.y, acc[0][1]);
            acc[0][2] = fmaf(a0, b.z, acc[0][2]); acc[0][3] = fmaf(a0, b.w, acc[0][3]);
            acc[1][0] = fmaf(a1, b.x, acc[1][0]); acc[1][1] = fmaf(a1, b.y, acc[1][1]);
            acc[1][2] = fmaf(a1, b.z, acc[1][2]); acc[1][3] = fmaf(a1, b.w, acc[1][3]);
            acc[2][0] = fmaf(a2, b.x, acc[2][0]); acc[2][1] = fmaf(a2, b.y, acc[2][1]);
            acc[2][2] = fmaf(a2, b.z, acc[2][2]); acc[2][3] = fmaf(a2, b.w, acc[2][3]);
            acc[3][0] = fmaf(a3, b.x, acc[3][0]); acc[3][1] = fmaf(a3, b.y, acc[3][1]);
            acc[3][2] = fmaf(a3, b.z, acc[3][2]); acc[3][3] = fmaf(a3, b.w, acc[3][3]);
        }
        __syncthreads();
    }
#pragma unroll
    for (int i = 0; i < 4; i++) {
        int r = row0 + ty * 4 + i;
        if (r < M) {
#pragma unroll
            for (int j = 0; j < 4; j++)
                C[r * N + col0 + tx * 4 + j] = acc[i][j];
        }
    }
}

// ---------------- alpha projections: per node, per head dot(h, a) -------------
__global__ void k_alpha(const float* __restrict__ h, const float* __restrict__ a_s,
                        const float* __restrict__ a_d, float* __restrict__ os,
                        float* __restrict__ od, int F)
{
    int n = blockIdx.x, f = threadIdx.x;
    float v = h[n * F + f];
    float ps = v * a_s[f];
    float pd = v * a_d[f];
#pragma unroll
    for (int o = 16; o > 0; o >>= 1) {
        ps += __shfl_down_sync(0xffffffffu, ps, o);
        pd += __shfl_down_sync(0xffffffffu, pd, o);
    }
    __shared__ float ss[8], sd[8];
    int w = f >> 5;
    if ((f & 31) == 0) { ss[w] = ps; sd[w] = pd; }
    __syncthreads();
    int nh = F >> 6;
    if (f < nh) {
        os[n * nh + f] = ss[2 * f] + ss[2 * f + 1];
        od[n * nh + f] = sd[2 * f] + sd[2 * f + 1];
    }
}

// ---------------- GAT aggregation, H=4 heads, F=256 ---------------------------
__global__ __launch_bounds__(256) void k_agg4(
    const float* __restrict__ h, const float* __restrict__ as, const float* __restrict__ ad,
    const float* __restrict__ bias, float* __restrict__ out, int elu)
{
    const int CH = 64;
    __shared__ int   s_src[CH];
    __shared__ float s_w[CH * 4];
    __shared__ float s_den[4];

    int n = blockIdx.x, f = threadIdx.x;
    int head = f >> 6, lane = f & 31, warp = f >> 5;
    int beg = g_off[n];
    int deg = g_off[n + 1] - beg;

    if (f < 4) s_den[f] = 0.f;
    __syncthreads();

    float4 adv = make_float4(0, 0, 0, 0);
    float m0 = -1e30f, m1 = -1e30f, m2 = -1e30f, m3 = -1e30f;
    if (warp == 0) {
        adv = *(const float4*)(ad + n * 4);
        for (int i = lane; i < deg; i += 32) {
            int s = g_srcs[beg + i];
            float4 av = *(const float4*)(as + s * 4);
            m0 = fmaxf(m0, lrelu(av.x + adv.x));
            m1 = fmaxf(m1, lrelu(av.y + adv.y));
            m2 = fmaxf(m2, lrelu(av.z + adv.z));
            m3 = fmaxf(m3, lrelu(av.w + adv.w));
        }
#pragma unroll
        for (int o = 16; o > 0; o >>= 1) {
            m0 = fmaxf(m0, __shfl_xor_sync(0xffffffffu, m0, o));
            m1 = fmaxf(m1, __shfl_xor_sync(0xffffffffu, m1, o));
            m2 = fmaxf(m2, __shfl_xor_sync(0xffffffffu, m2, o));
            m3 = fmaxf(m3, __shfl_xor_sync(0xffffffffu, m3, o));
        }
    }

    float acc = 0.f;
    for (int base = 0; base < deg; base += CH) {
        int cnt = min(CH, deg - base);
        if (warp == 0) {
            float d0 = 0, d1 = 0, d2 = 0, d3 = 0;
            for (int i = lane; i < cnt; i += 32) {
                int s = g_srcs[beg + base + i];
                s_src[i] = s;
                float4 av = *(const float4*)(as + s * 4);
                float w0 = __expf(lrelu(av.x + adv.x) - m0);
                float w1 = __expf(lrelu(av.y + adv.y) - m1);
                float w2 = __expf(lrelu(av.z + adv.z) - m2);
                float w3 = __expf(lrelu(av.w + adv.w) - m3);
                s_w[i * 4 + 0] = w0; s_w[i * 4 + 1] = w1;
                s_w[i * 4 + 2] = w2; s_w[i * 4 + 3] = w3;
                d0 += w0; d1 += w1; d2 += w2; d3 += w3;
            }
#pragma unroll
            for (int o = 16; o > 0; o >>= 1) {
                d0 += __shfl_xor_sync(0xffffffffu, d0, o);
                d1 += __shfl_xor_sync(0xffffffffu, d1, o);
                d2 += __shfl_xor_sync(0xffffffffu, d2, o);
                d3 += __shfl_xor_sync(0xffffffffu, d3, o);
            }
            if (lane == 0) { s_den[0] += d0; s_den[1] += d1; s_den[2] += d2; s_den[3] += d3; }
        }
        __syncthreads();
        int i = 0;
        for (; i + 4 <= cnt; i += 4) {
            int   sa = s_src[i + 0], sb = s_src[i + 1], sc = s_src[i + 2], sd2 = s_src[i + 3];
            float wa = s_w[(i + 0) * 4 + head], wb = s_w[(i + 1) * 4 + head];
            float wc = s_w[(i + 2) * 4 + head], wd = s_w[(i + 3) * 4 + head];
            float va = h[sa * 256 + f], vb = h[sb * 256 + f];
            float vc = h[sc * 256 + f], vd = h[sd2 * 256 + f];
            acc = fmaf(va, wa, acc);
            acc = fmaf(vb, wb, acc);
            acc = fmaf(vc, wc, acc);
            acc = fmaf(vd, wd, acc);
        }
        for (; i < cnt; i++)
            acc = fmaf(h[s_src[i] * 256 + f], s_w[i * 4 + head], acc);
        __syncthreads();
    }

    float den = s_den[head] + 1e-16f;
    float o = acc / den + bias[f];
    if (elu) o = o > 0.f ? o : expm1f(o);
    out[n * 256 + f] = o;
}

// ---------------- GAT aggregation, H=1, F=64 (layer 3) ------------------------
__global__ __launch_bounds__(64) void k_agg1(
    const float* __restrict__ h, const float* __restrict__ as, const float* __restrict__ ad,
    const float* __restrict__ bias, float* __restrict__ out)
{
    const int CH = 64;
    __shared__ int   s_src[CH];
    __shared__ float s_w[CH];
    __shared__ float s_den;

    int n = blockIdx.x, f = threadIdx.x;
    int lane = f & 31, warp = f >> 5;
    int beg = g_off[n];
    int deg = g_off[n + 1] - beg;

    if (f == 0) s_den = 0.f;
    __syncthreads();

    float advv = 0.f, m = -1e30f;
    if (warp == 0) {
        advv = ad[n];
        for (int i = lane; i < deg; i += 32)
            m = fmaxf(m, lrelu(as[g_srcs[beg + i]] + advv));
#pragma unroll
        for (int o = 16; o > 0; o >>= 1)
            m = fmaxf(m, __shfl_xor_sync(0xffffffffu, m, o));
    }

    float acc = 0.f;
    for (int base = 0; base < deg; base += CH) {
        int cnt = min(CH, deg - base);
        if (warp == 0) {
            float d = 0.f;
            for (int i = lane; i < cnt; i += 32) {
                int s = g_srcs[beg + base + i];
                s_src[i] = s;
                float w = __expf(lrelu(as[s] + advv) - m);
                s_w[i] = w;
                d += w;
            }
#pragma unroll
            for (int o = 16; o > 0; o >>= 1)
                d += __shfl_xor_sync(0xffffffffu, d, o);
            if (lane == 0) s_den += d;
        }
        __syncthreads();
        int i = 0;
        for (; i + 4 <= cnt; i += 4) {
            acc = fmaf(h[s_src[i + 0] * 64 + f], s_w[i + 0], acc);
            acc = fmaf(h[s_src[i + 1] * 64 + f], s_w[i + 1], acc);
            acc = fmaf(h[s_src[i + 2] * 64 + f], s_w[i + 2], acc);
            acc = fmaf(h[s_src[i + 3] * 64 + f], s_w[i + 3], acc);
        }
        for (; i < cnt; i++)
            acc = fmaf(h[s_src[i] * 64 + f], s_w[i], acc);
        __syncthreads();
    }
    out[n * 64 + f] = acc / (s_den + 1e-16f) + bias[f];
}

// ---------------- mean pool over sorted batch ids ----------------------------
__global__ void k_pool(const float* __restrict__ node, const int* __restrict__ batch,
                       float* __restrict__ gout, int n)
{
    int g = blockIdx.x;
    int lo = 0, hi = n;
    while (lo < hi) { int mid = (lo + hi) >> 1; if (batch[mid] < g) lo = mid + 1; else hi = mid; }
    int start = lo;
    lo = start; hi = n;
    while (lo < hi) { int mid = (lo + hi) >> 1; if (batch[mid] < g + 1) lo = mid + 1; else hi = mid; }
    int end = lo;

    int f = threadIdx.x & 63;
    int sub = threadIdx.x >> 6;          // 4 subgroups
    float acc = 0.f;
    for (int i = start + sub; i < end; i += 4)
        acc += node[i * 64 + f];
    __shared__ float s[256];
    s[threadIdx.x] = acc;
    __syncthreads();
    if (threadIdx.x < 64) {
        float v = s[threadIdx.x] + s[threadIdx.x + 64] + s[threadIdx.x + 128] + s[threadIdx.x + 192];
        int cnt = end - start;
        gout[g * 64 + threadIdx.x] = v / (float)max(cnt, 1);
    }
}

// ---------------- host side ---------------------------------------------------
extern "C" void kernel_launch(void* const* d_in, const int* in_sizes, int n_in,
                              void* d_out, int out_size)
{
    const float* x    = (const float*)d_in[0];
    const int*   ei   = (const int*)d_in[1];
    const int*   batch= (const int*)d_in[2];
    const float* W1   = (const float*)d_in[3];
    const float* as1  = (const float*)d_in[4];
    const float* ad1  = (const float*)d_in[5];
    const float* b1   = (const float*)d_in[6];
    const float* W2   = (const float*)d_in[7];
    const float* as2  = (const float*)d_in[8];
    const float* ad2  = (const float*)d_in[9];
    const float* b2   = (const float*)d_in[10];
    const float* W3   = (const float*)d_in[11];
    const float* as3  = (const float*)d_in[12];
    const float* ad3  = (const float*)d_in[13];
    const float* b3   = (const float*)d_in[14];

    int n = in_sizes[0] / 256;
    int E = in_sizes[1] / 2;
    float* out = (float*)d_out;
    int G = (out_size - n * 64) / 64;

    float *p_h, *p_h2, *p_as, *p_ad;
    cudaGetSymbolAddress((void**)&p_h,  g_h);
    cudaGetSymbolAddress((void**)&p_h2, g_h2);
    cudaGetSymbolAddress((void**)&p_as, g_as);
    cudaGetSymbolAddress((void**)&p_ad, g_ad);

    int tot = E + n;
    k_zero<<<(n + 255) / 256, 256>>>(n);
    k_deg<<<(tot + 255) / 256, 256>>>(ei, E, n);
    k_scan<<<1, 1024>>>(n);
    k_scatter<<<(tot + 255) / 256, 256>>>(ei, E, n);

    dim3 gbig(256 / 64, (n + 63) / 64);
    dim3 gsm(64 / 64, (n + 63) / 64);

    // layer 1
    k_gemm<<<gbig, 256>>>(x, W1, p_h2, n, 256, 256);
    k_alpha<<<n, 256>>>(p_h2, as1, ad1, p_as, p_ad, 256);
    k_agg4<<<n, 256>>>(p_h2, p_as, p_ad, b1, p_h, 1);
    // layer 2
    k_gemm<<<gbig, 256>>>(p_h, W2, p_h2, n, 256, 256);
    k_alpha<<<n, 256>>>(p_h2, as2, ad2, p_as, p_ad, 256);
    k_agg4<<<n, 256>>>(p_h2, p_as, p_ad, b2, p_h, 1);
    // layer 3
    k_gemm<<<gsm, 256>>>(p_h, W3, p_h2, n, 64, 256);
    k_alpha<<<n, 64>>>(p_h2, as3, ad3, p_as, p_ad, 64);
    k_agg1<<<n, 64>>>(p_h2, p_as, p_ad, b3, out);
    // pooling
    k_pool<<<G, 256>>>(out, batch, out + n * 64, n);
}

// round 2
// speedup vs baseline: 1.2676x; 1.2676x over previous
#include <cuda_runtime.h>
#include <math.h>
#include <mma.h>
using namespace nvcuda;

#define NMAX 50000
#define EMAX 800000
#define EPMAX (EMAX + NMAX)
#define FH 256
#define NHEADS 4
#define NBPART ((NMAX + 1023) / 1024)

// ---------------- scratch (device globals; no runtime alloc allowed) ----------
__device__ float g_h[NMAX * FH];      // activation ping
__device__ float g_h2[NMAX * FH];     // activation pong (pre-aggregation h)
__device__ float g_as[NMAX * NHEADS]; // alpha_src per node
__device__ float g_ad[NMAX * NHEADS]; // alpha_dst per node
__device__ int   g_off[NMAX + 1];     // CSR row offsets (by dst)
__device__ int   g_deg[NMAX];
__device__ int   g_cur[NMAX];
__device__ int   g_srcs[EPMAX];       // CSR column indices (src node per edge)
__device__ int   g_part[NBPART];      // per-block degree partial sums
__device__ int   g_ppre[NBPART];      // exclusive prefix of partials

__device__ __forceinline__ float lrelu(float x) { return x > 0.f ? x : 0.2f * x; }

// ---------------- CSR build ---------------------------------------------------
__global__ void k_zero(int n) {
    int i = blockIdx.x * blockDim.x + threadIdx.x;
    if (i < n) { g_deg[i] = 0; g_cur[i] = 0; }
}

__global__ void k_deg(const int* __restrict__ ei, int E, int n) {
    int i = blockIdx.x * blockDim.x + threadIdx.x;
    int tot = E + n;
    if (i < tot) {
        int dst = (i < E) ? ei[E + i] : (i - E);   // self-loops appended
        atomicAdd(&g_deg[dst], 1);
    }
}

// per-1024-chunk partial sums
__global__ __launch_bounds__(1024) void k_part(int n) {
    __shared__ int s[1024];
    int i = blockIdx.x * 1024 + threadIdx.x;
    s[threadIdx.x] = (i < n) ? g_deg[i] : 0;
    __syncthreads();
    for (int off = 512; off > 0; off >>= 1) {
        if (threadIdx.x < off) s[threadIdx.x] += s[threadIdx.x + off];
        __syncthreads();
    }
    if (threadIdx.x == 0) g_part[blockIdx.x] = s[0];
}

// tiny scan over partials (single block)
__global__ void k_scanp(int nb) {
    __shared__ int s[NBPART];
    int tid = threadIdx.x;
    if (tid < nb) s[tid] = g_part[tid];
    __syncthreads();
    if (tid == 0) {
        int run = 0;
        for (int i = 0; i < nb; i++) { g_ppre[i] = run; run += s[i]; }
    }
}

// per-chunk inclusive scan + partial offset -> g_off
__global__ __launch_bounds__(1024) void k_offsets(int n) {
    __shared__ int s[1024];
    int b = blockIdx.x;
    int i = b * 1024 + threadIdx.x;
    int v = (i < n) ? g_deg[i] : 0;
    s[threadIdx.x] = v;
    __syncthreads();
    for (int off = 1; off < 1024; off <<= 1) {
        int t = (threadIdx.x >= off) ? s[threadIdx.x - off] : 0;
        __syncthreads();
        s[threadIdx.x] += t;
        __syncthreads();
    }
    if (i < n) g_off[i + 1] = g_ppre[b] + s[threadIdx.x];
    if (b == 0 && threadIdx.x == 0) g_off[0] = 0;
}

__global__ void k_scatter(const int* __restrict__ ei, int E, int n) {
    int i = blockIdx.x * blockDim.x + threadIdx.x;
    int tot = E + n;
    if (i < tot) {
        int src, dst;
        if (i < E) { src = ei[i]; dst = ei[E + i]; }
        else       { src = i - E; dst = src; }
        int pos = g_off[dst] + atomicAdd(&g_cur[dst], 1);
        g_srcs[pos] = src;
    }
}

// ---------------- GEMM: C[M,N] = A[M,K] * B[K,N]  (tf32 tensor cores) ---------
// 64x64 block tile, K-chunk 32, 8 warps: warp (r,c2) computes 16x32.
__global__ __launch_bounds__(256) void k_gemm_tc(
    const float* __restrict__ A, const float* __restrict__ B, float* __restrict__ C,
    int M, int N, int K)
{
    __shared__ float As[64][36];
    __shared__ float Bs[32][68];
    __shared__ float Cs[64][68];

    int tid = threadIdx.x;
    int warp = tid >> 5;
    int row0 = blockIdx.y * 64, col0 = blockIdx.x * 64;
    int wr = (warp & 3) * 16;
    int wc = (warp >> 2) * 32;

    wmma::fragment<wmma::accumulator, 16, 16, 8, float> c0, c1;
    wmma::fill_fragment(c0, 0.f);
    wmma::fill_fragment(c1, 0.f);

    for (int k0 = 0; k0 < K; k0 += 32) {
#pragma unroll
        for (int r = 0; r < 2; r++) {
            int idx = tid + r * 256;          // 512 float4 slots for 64x32
            int m = idx >> 3;
            int kk = (idx & 7) * 4;
            float4 v = make_float4(0.f, 0.f, 0.f, 0.f);
            if (row0 + m < M) v = *(const float4*)&A[(size_t)(row0 + m) * K + k0 + kk];
            As[m][kk + 0] = wmma::__float_to_tf32(v.x);
            As[m][kk + 1] = wmma::__float_to_tf32(v.y);
            As[m][kk + 2] = wmma::__float_to_tf32(v.z);
            As[m][kk + 3] = wmma::__float_to_tf32(v.w);
        }
#pragma unroll
        for (int r = 0; r < 2; r++) {
            int idx = tid + r * 256;          // 512 float4 slots for 32x64
            int kk = idx >> 4;
            int nn = (idx & 15) * 4;
            float4 v = *(const float4*)&B[(size_t)(k0 + kk) * N + col0 + nn];
            Bs[kk][nn + 0] = wmma::__float_to_tf32(v.x);
            Bs[kk][nn + 1] = wmma::__float_to_tf32(v.y);
            Bs[kk][nn + 2] = wmma::__float_to_tf32(v.z);
            Bs[kk][nn + 3] = wmma::__float_to_tf32(v.w);
        }
        __syncthreads();
#pragma unroll
        for (int kk = 0; kk < 32; kk += 8) {
            wmma::fragment<wmma::matrix_a, 16, 16, 8, wmma::precision::tf32, wmma::row_major> a;
            wmma::fragment<wmma::matrix_b, 16, 16, 8, wmma::precision::tf32, wmma::row_major> b0, b1;
            wmma::load_matrix_sync(a, &As[wr][kk], 36);
            wmma::load_matrix_sync(b0, &Bs[kk][wc], 68);
            wmma::load_matrix_sync(b1, &Bs[kk][wc + 16], 68);
            wmma::mma_sync(c0, a, b0, c0);
            wmma::mma_sync(c1, a, b1, c1);
        }
        __syncthreads();
    }

    if (row0 + 64 <= M) {
        wmma::store_matrix_sync(&C[(size_t)(row0 + wr) * N + col0 + wc], c0, N, wmma::mem_row_major);
        wmma::store_matrix_sync(&C[(size_t)(row0 + wr) * N + col0 + wc + 16], c1, N, wmma::mem_row_major);
    } else {
        wmma::store_matrix_sync(&Cs[wr][wc], c0, 68, wmma::mem_row_major);
        wmma::store_matrix_sync(&Cs[wr][wc + 16], c1, 68, wmma::mem_row_major);
        __syncthreads();
        for (int idx = tid; idx < 64 * 64; idx += 256) {
            int m = idx >> 6, nn = idx & 63;
            if (row0 + m < M) C[(size_t)(row0 + m) * N + col0 + nn] = Cs[m][nn];
        }
    }
}

// ---------------- alpha projections: per node, per head dot(h, a) -------------
__global__ void k_alpha(const float* __restrict__ h, const float* __restrict__ a_s,
                        const float* __restrict__ a_d, float* __restrict__ os,
                        float* __restrict__ od, int F)
{
    int n = blockIdx.x, f = threadIdx.x;
    float v = h[n * F + f];
    float ps = v * a_s[f];
    float pd = v * a_d[f];
#pragma unroll
    for (int o = 16; o > 0; o >>= 1) {
        ps += __shfl_down_sync(0xffffffffu, ps, o);
        pd += __shfl_down_sync(0xffffffffu, pd, o);
    }
    __shared__ float ss[8], sd[8];
    int w = f >> 5;
    if ((f & 31) == 0) { ss[w] = ps; sd[w] = pd; }
    __syncthreads();
    int nh = F >> 6;
    if (f < nh) {
        os[n * nh + f] = ss[2 * f] + ss[2 * f + 1];
        od[n * nh + f] = sd[2 * f] + sd[2 * f + 1];
    }
}

// ---------------- GAT aggregation, H=4 heads, F=256 ---------------------------
__global__ __launch_bounds__(256) void k_agg4(
    const float* __restrict__ h, const float* __restrict__ as, const float* __restrict__ ad,
    const float* __restrict__ bias, float* __restrict__ out, int elu)
{
    const int CH = 64;
    __shared__ int   s_src[CH];
    __shared__ float s_w[CH * 4];
    __shared__ float s_den[4];

    int n = blockIdx.x, f = threadIdx.x;
    int head = f >> 6, lane = f & 31, warp = f >> 5;
    int beg = g_off[n];
    int deg = g_off[n + 1] - beg;

    if (f < 4) s_den[f] = 0.f;
    __syncthreads();

    float4 adv = make_float4(0, 0, 0, 0);
    float m0 = -1e30f, m1 = -1e30f, m2 = -1e30f, m3 = -1e30f;
    if (warp == 0) {
        adv = *(const float4*)(ad + n * 4);
        for (int i = lane; i < deg; i += 32) {
            int s = g_srcs[beg + i];
            float4 av = *(const float4*)(as + s * 4);
            m0 = fmaxf(m0, lrelu(av.x + adv.x));
            m1 = fmaxf(m1, lrelu(av.y + adv.y));
            m2 = fmaxf(m2, lrelu(av.z + adv.z));
            m3 = fmaxf(m3, lrelu(av.w + adv.w));
        }
#pragma unroll
        for (int o = 16; o > 0; o >>= 1) {
            m0 = fmaxf(m0, __shfl_xor_sync(0xffffffffu, m0, o));
            m1 = fmaxf(m1, __shfl_xor_sync(0xffffffffu, m1, o));
            m2 = fmaxf(m2, __shfl_xor_sync(0xffffffffu, m2, o));
            m3 = fmaxf(m3, __shfl_xor_sync(0xffffffffu, m3, o));
        }
    }

    float acc = 0.f;
    for (int base = 0; base < deg; base += CH) {
        int cnt = min(CH, deg - base);
        if (warp == 0) {
            float d0 = 0, d1 = 0, d2 = 0, d3 = 0;
            for (int i = lane; i < cnt; i += 32) {
                int s = g_srcs[beg + base + i];
                s_src[i] = s;
                float4 av = *(const float4*)(as + s * 4);
                float w0 = __expf(lrelu(av.x + adv.x) - m0);
                float w1 = __expf(lrelu(av.y + adv.y) - m1);
                float w2 = __expf(lrelu(av.z + adv.z) - m2);
                float w3 = __expf(lrelu(av.w + adv.w) - m3);
                s_w[i * 4 + 0] = w0; s_w[i * 4 + 1] = w1;
                s_w[i * 4 + 2] = w2; s_w[i * 4 + 3] = w3;
                d0 += w0; d1 += w1; d2 += w2; d3 += w3;
            }
#pragma unroll
            for (int o = 16; o > 0; o >>= 1) {
                d0 += __shfl_xor_sync(0xffffffffu, d0, o);
                d1 += __shfl_xor_sync(0xffffffffu, d1, o);
                d2 += __shfl_xor_sync(0xffffffffu, d2, o);
                d3 += __shfl_xor_sync(0xffffffffu, d3, o);
            }
            if (lane == 0) { s_den[0] += d0; s_den[1] += d1; s_den[2] += d2; s_den[3] += d3; }
        }
        __syncthreads();
        int i = 0;
        for (; i + 4 <= cnt; i += 4) {
            int   sa = s_src[i + 0], sb = s_src[i + 1], sc = s_src[i + 2], sd2 = s_src[i + 3];
            float wa = s_w[(i + 0) * 4 + head], wb = s_w[(i + 1) * 4 + head];
            float wc = s_w[(i + 2) * 4 + head], wd = s_w[(i + 3) * 4 + head];
            float va = h[sa * 256 + f], vb = h[sb * 256 + f];
            float vc = h[sc * 256 + f], vd = h[sd2 * 256 + f];
            acc = fmaf(va, wa, acc);
            acc = fmaf(vb, wb, acc);
            acc = fmaf(vc, wc, acc);
            acc = fmaf(vd, wd, acc);
        }
        for (; i < cnt; i++)
            acc = fmaf(h[s_src[i] * 256 + f], s_w[i * 4 + head], acc);
        __syncthreads();
    }

    float den = s_den[head] + 1e-16f;
    float o = acc / den + bias[f];
    if (elu) o = o > 0.f ? o : expm1f(o);
    out[n * 256 + f] = o;
}

// ---------------- GAT aggregation, H=1, F=64 (layer 3) ------------------------
__global__ __launch_bounds__(64) void k_agg1(
    const float* __restrict__ h, const float* __restrict__ as, const float* __restrict__ ad,
    const float* __restrict__ bias, float* __restrict__ out)
{
    const int CH = 64;
    __shared__ int   s_src[CH];
    __shared__ float s_w[CH];
    __shared__ float s_den;

    int n = blockIdx.x, f = threadIdx.x;
    int lane = f & 31, warp = f >> 5;
    int beg = g_off[n];
    int deg = g_off[n + 1] - beg;

    if (f == 0) s_den = 0.f;
    __syncthreads();

    float advv = 0.f, m = -1e30f;
    if (warp == 0) {
        advv = ad[n];
        for (int i = lane; i < deg; i += 32)
            m = fmaxf(m, lrelu(as[g_srcs[beg + i]] + advv));
#pragma unroll
        for (int o = 16; o > 0; o >>= 1)
            m = fmaxf(m, __shfl_xor_sync(0xffffffffu, m, o));
    }

    float acc = 0.f;
    for (int base = 0; base < deg; base += CH) {
        int cnt = min(CH, deg - base);
        if (warp == 0) {
            float d = 0.f;
            for (int i = lane; i < cnt; i += 32) {
                int s = g_srcs[beg + base + i];
                s_src[i] = s;
                float w = __expf(lrelu(as[s] + advv) - m);
                s_w[i] = w;
                d += w;
            }
#pragma unroll
            for (int o = 16; o > 0; o >>= 1)
                d += __shfl_xor_sync(0xffffffffu, d, o);
            if (lane == 0) s_den += d;
        }
        __syncthreads();
        int i = 0;
        for (; i + 4 <= cnt; i += 4) {
            acc = fmaf(h[s_src[i + 0] * 64 + f], s_w[i + 0], acc);
            acc = fmaf(h[s_src[i + 1] * 64 + f], s_w[i + 1], acc);
            acc = fmaf(h[s_src[i + 2] * 64 + f], s_w[i + 2], acc);
            acc = fmaf(h[s_src[i + 3] * 64 + f], s_w[i + 3], acc);
        }
        for (; i < cnt; i++)
            acc = fmaf(h[s_src[i] * 64 + f], s_w[i], acc);
        __syncthreads();
    }
    out[n * 64 + f] = acc / (s_den + 1e-16f) + bias[f];
}

// ---------------- mean pool over sorted batch ids ----------------------------
__global__ void k_pool(const float* __restrict__ node, const int* __restrict__ batch,
                       float* __restrict__ gout, int n)
{
    int g = blockIdx.x;
    int lo = 0, hi = n;
    while (lo < hi) { int mid = (lo + hi) >> 1; if (batch[mid] < g) lo = mid + 1; else hi = mid; }
    int start = lo;
    lo = start; hi = n;
    while (lo < hi) { int mid = (lo + hi) >> 1; if (batch[mid] < g + 1) lo = mid + 1; else hi = mid; }
    int end = lo;

    int f = threadIdx.x & 63;
    int sub = threadIdx.x >> 6;          // 4 subgroups
    float acc = 0.f;
    for (int i = start + sub; i < end; i += 4)
        acc += node[i * 64 + f];
    __shared__ float s[256];
    s[threadIdx.x] = acc;
    __syncthreads();
    if (threadIdx.x < 64) {
        float v = s[threadIdx.x] + s[threadIdx.x + 64] + s[threadIdx.x + 128] + s[threadIdx.x + 192];
        int cnt = end - start;
        gout[g * 64 + threadIdx.x] = v / (float)max(cnt, 1);
    }
}

// ---------------- host side ---------------------------------------------------
extern "C" void kernel_launch(void* const* d_in, const int* in_sizes, int n_in,
                              void* d_out, int out_size)
{
    const float* x    = (const float*)d_in[0];
    const int*   ei   = (const int*)d_in[1];
    const int*   batch= (const int*)d_in[2];
    const float* W1   = (const float*)d_in[3];
    const float* as1  = (const float*)d_in[4];
    const float* ad1  = (const float*)d_in[5];
    const float* b1   = (const float*)d_in[6];
    const float* W2   = (const float*)d_in[7];
    const float* as2  = (const float*)d_in[8];
    const float* ad2  = (const float*)d_in[9];
    const float* b2   = (const float*)d_in[10];
    const float* W3   = (const float*)d_in[11];
    const float* as3  = (const float*)d_in[12];
    const float* ad3  = (const float*)d_in[13];
    const float* b3   = (const float*)d_in[14];

    int n = in_sizes[0] / 256;
    int E = in_sizes[1] / 2;
    float* out = (float*)d_out;
    int G = (out_size - n * 64) / 64;

    float *p_h, *p_h2, *p_as, *p_ad;
    cudaGetSymbolAddress((void**)&p_h,  g_h);
    cudaGetSymbolAddress((void**)&p_h2, g_h2);
    cudaGetSymbolAddress((void**)&p_as, g_as);
    cudaGetSymbolAddress((void**)&p_ad, g_ad);

    int tot = E + n;
    int nb = (n + 1023) / 1024;
    k_zero<<<(n + 255) / 256, 256>>>(n);
    k_deg<<<(tot + 255) / 256, 256>>>(ei, E, n);
    k_part<<<nb, 1024>>>(n);
    k_scanp<<<1, 64>>>(nb);
    k_offsets<<<nb, 1024>>>(n);
    k_scatter<<<(tot + 255) / 256, 256>>>(ei, E, n);

    dim3 gbig(256 / 64, (n + 63) / 64);
    dim3 gsm(1, (n + 63) / 64);

    // layer 1
    k_gemm_tc<<<gbig, 256>>>(x, W1, p_h2, n, 256, 256);
    k_alpha<<<n, 256>>>(p_h2, as1, ad1, p_as, p_ad, 256);
    k_agg4<<<n, 256>>>(p_h2, p_as, p_ad, b1, p_h, 1);
    // layer 2
    k_gemm_tc<<<gbig, 256>>>(p_h, W2, p_h2, n, 256, 256);
    k_alpha<<<n, 256>>>(p_h2, as2, ad2, p_as, p_ad, 256);
    k_agg4<<<n, 256>>>(p_h2, p_as, p_ad, b2, p_h, 1);
    // layer 3
    k_gemm_tc<<<gsm, 256>>>(p_h, W3, p_h2, n, 64, 256);
    k_alpha<<<n, 64>>>(p_h2, as3, ad3, p_as, p_ad, 64);
    k_agg1<<<n, 64>>>(p_h2, p_as, p_ad, b3, out);
    // pooling
    k_pool<<<G, 256>>>(out, batch, out + n * 64, n);
}